// round 1
// baseline (speedup 1.0000x reference)
#include <cuda_runtime.h>

#define D     256
#define BOOK  8192
#define MT    128     // queries per CTA
#define NT    128     // codes per chunk
#define KT    32      // K slice for code double-buffer
#define HW    1024    // 32*32 spatial positions per batch

#define SMEM_BYTES ((D * MT + 2 * KT * NT) * 4)   // 163840 B

__device__ float g_enorm[BOOK];

// ||e||^2 per codebook row. One 64-thread block per code.
__global__ void __launch_bounds__(64) enorm_kernel(const float* __restrict__ cb) {
    int c = blockIdx.x;
    float4 v = reinterpret_cast<const float4*>(cb + (size_t)c * D)[threadIdx.x];
    float s = v.x * v.x + v.y * v.y + v.z * v.z + v.w * v.w;
#pragma unroll
    for (int o = 16; o > 0; o >>= 1) s += __shfl_down_sync(0xffffffffu, s, o);
    __shared__ float sh[2];
    if ((threadIdx.x & 31) == 0) sh[threadIdx.x >> 5] = s;
    __syncthreads();
    if (threadIdx.x == 0) g_enorm[c] = sh[0] + sh[1];
}

extern __shared__ float smem[];

__global__ void __launch_bounds__(256, 1) vq_kernel(
    const float* __restrict__ ze, const float* __restrict__ cb,
    float* __restrict__ out, int N, int write_idx)
{
    float* zs = smem;               // [256][128] query tile, transposed (k-major)
    float* es = smem + D * MT;      // [2][32][128] code slice double buffer

    const int tid = threadIdx.x;
    const int tx = tid & 15;
    const int ty = tid >> 4;
    const int n0 = blockIdx.x * MT;
    const int b   = n0 / HW;
    const int hwb = n0 % HW;
    const float* zbase = ze + (size_t)b * D * HW + hwb;

    // Load z tile: zs[k][q] = z_e[b][k][hwb+q]  (coalesced: q contiguous in gmem)
    {
        int w = tid >> 5, l = tid & 31;
        for (int k = w; k < D; k += 8) {
            float4 v = *reinterpret_cast<const float4*>(zbase + (size_t)k * HW + l * 4);
            *reinterpret_cast<float4*>(&zs[k * MT + l * 4]) = v;
        }
    }

    const int qa = ty * 4, qb = 64 + ty * 4;    // 8 query rows per thread
    const int ca = tx * 4, cc = 64 + tx * 4;    // 8 code cols per thread

    float bestv[8];
    int   besti[8];
#pragma unroll
    for (int i = 0; i < 8; i++) { bestv[i] = 3.0e38f; besti[i] = 0; }

    const int cld   = tid >> 1;          // code row this thread stages
    const int khalf = (tid & 1) * 16;    // k offset within slice

    __syncthreads();

    for (int c0 = 0; c0 < BOOK; c0 += NT) {
        float acc[8][8];
#pragma unroll
        for (int i = 0; i < 8; i++)
#pragma unroll
            for (int j = 0; j < 8; j++) acc[i][j] = 0.f;

        // Preload slice ks=0 into buffer 0 (transpose: es[k][c])
        {
            const float* src = cb + (size_t)(c0 + cld) * D + khalf;
#pragma unroll
            for (int v4 = 0; v4 < 4; v4++) {
                float4 v = *reinterpret_cast<const float4*>(src + v4 * 4);
                es[(khalf + v4 * 4 + 0) * NT + cld] = v.x;
                es[(khalf + v4 * 4 + 1) * NT + cld] = v.y;
                es[(khalf + v4 * 4 + 2) * NT + cld] = v.z;
                es[(khalf + v4 * 4 + 3) * NT + cld] = v.w;
            }
        }
        __syncthreads();

        int buf = 0;
        for (int ks = 0; ks < D; ks += KT) {
            if (ks + KT < D) {  // prefetch next slice into other buffer
                float* ed = es + (buf ^ 1) * KT * NT;
                const float* src = cb + (size_t)(c0 + cld) * D + ks + KT + khalf;
#pragma unroll
                for (int v4 = 0; v4 < 4; v4++) {
                    float4 v = *reinterpret_cast<const float4*>(src + v4 * 4);
                    ed[(khalf + v4 * 4 + 0) * NT + cld] = v.x;
                    ed[(khalf + v4 * 4 + 1) * NT + cld] = v.y;
                    ed[(khalf + v4 * 4 + 2) * NT + cld] = v.z;
                    ed[(khalf + v4 * 4 + 3) * NT + cld] = v.w;
                }
            }
            const float* eb = es + buf * KT * NT;
#pragma unroll 8
            for (int k = 0; k < KT; k++) {
                const float* zr = &zs[(ks + k) * MT];
                float4 a0 = *reinterpret_cast<const float4*>(zr + qa);
                float4 a1 = *reinterpret_cast<const float4*>(zr + qb);
                float4 b0 = *reinterpret_cast<const float4*>(eb + k * NT + ca);
                float4 b1 = *reinterpret_cast<const float4*>(eb + k * NT + cc);
                float av[8] = {a0.x, a0.y, a0.z, a0.w, a1.x, a1.y, a1.z, a1.w};
                float bv[8] = {b0.x, b0.y, b0.z, b0.w, b1.x, b1.y, b1.z, b1.w};
#pragma unroll
                for (int i = 0; i < 8; i++)
#pragma unroll
                    for (int j = 0; j < 8; j++)
                        acc[i][j] = fmaf(av[i], bv[j], acc[i][j]);
            }
            __syncthreads();
            buf ^= 1;
        }

        // Score = ||e||^2 - 2*dot ; update running argmin (ascending code index
        // within the thread's set -> strict '<' keeps first occurrence)
#pragma unroll
        for (int j = 0; j < 8; j++) {
            int c = c0 + (j < 4 ? ca + j : cc + (j - 4));
            float en = __ldg(&g_enorm[c]);
#pragma unroll
            for (int i = 0; i < 8; i++) {
                float s = fmaf(-2.0f, acc[i][j], en);
                if (s < bestv[i]) { bestv[i] = s; besti[i] = c; }
            }
        }
    }

    // Cross-thread argmin reduction (reuse zs region)
    float* redv = zs;                         // [128][16]
    int*   redi = (int*)(zs + MT * 16);       // [128][16]
    int*   bi   = (int*)(zs + MT * 32);       // [128]
    __syncthreads();
#pragma unroll
    for (int i = 0; i < 8; i++) {
        int q = (i < 4) ? (qa + i) : (qb + i - 4);
        redv[q * 16 + tx] = bestv[i];
        redi[q * 16 + tx] = besti[i];
    }
    __syncthreads();
    if (tid < MT) {
        int q = tid;
        float bv = redv[q * 16];
        int   bx = redi[q * 16];
#pragma unroll
        for (int t = 1; t < 16; t++) {
            float v  = redv[q * 16 + t];
            int   ix = redi[q * 16 + t];
            if (v < bv || (v == bv && ix < bx)) { bv = v; bx = ix; }
        }
        bi[q] = bx;
        if (write_idx) out[(size_t)N * D + n0 + q] = (float)bx;
    }
    __syncthreads();

    // Gather z_q rows: out[n] = codebook[bi[q]] (coalesced float4 copy)
    const float4* cb4  = reinterpret_cast<const float4*>(cb);
    float4*       out4 = reinterpret_cast<float4*>(out);
    for (int e = tid; e < MT * (D / 4); e += 256) {
        int q = e >> 6;       // row within tile
        int p = e & 63;       // float4 within row
        int idx = bi[q];
        out4[(size_t)(n0 + q) * (D / 4) + p] = cb4[(size_t)idx * (D / 4) + p];
    }
}

extern "C" void kernel_launch(void* const* d_in, const int* in_sizes, int n_in,
                              void* d_out, int out_size) {
    const float* ze = (const float*)d_in[0];
    const float* cb = (const float*)d_in[1];
    float* out = (float*)d_out;

    int N = in_sizes[0] / D;                       // 16384
    int write_idx = (out_size >= N * D + N) ? 1 : 0;

    cudaFuncSetAttribute(vq_kernel, cudaFuncAttributeMaxDynamicSharedMemorySize,
                         SMEM_BYTES);

    enorm_kernel<<<BOOK, 64>>>(cb);
    vq_kernel<<<N / MT, 256, SMEM_BYTES>>>(ze, cb, out, N, write_idx);
}